// round 12
// baseline (speedup 1.0000x reference)
#include <cuda_runtime.h>
#include <cstdint>

// FINAL (R8 configuration, measured best: ncu 6.048us).
// YOLO decode, 3 scales fused, unified global-cell indexing (grid=444=3*148).
// 1 thread = 1 cell, 15 front-batched coalesced loads (L2-resident in steady
// state), smem staging, per-warp cp.async.bulk (1920 B) copy-out with
// independent warp retirement (no block barrier). Epilogue addresses are
// computed AFTER the decode epoch (hoisting them regressed in R10).

#define TPB 256

__device__ __forceinline__ uint32_t smem_u32(const void* p) {
    return (uint32_t)__cvta_generic_to_shared(p);
}

template<int HW, int W, int TT,
         int AW0, int AH0, int AW1, int AH1, int AW2, int AH2>
__device__ __forceinline__ void decode_scale(const float* __restrict__ in,
                                             int c, float* __restrict__ so,
                                             float thresh)
{
    const int b  = c / HW;            // constexpr -> mul+shift
    const int hw = c - b * HW;
    const int h  = hw / W;
    const int w  = hw - h * W;

    const float* __restrict__ base = in + b * (255 * HW) + hw;
    const float* __restrict__ p0 = base;
    const float* __restrict__ p1 = base + 85  * HW;
    const float* __restrict__ p2 = base + 170 * HW;

    // 15 independent coalesced loads in flight.
    const float c0 = p0[0];
    const float x0 = p0[HW], y0 = p0[2*HW], w0 = p0[3*HW], h0 = p0[4*HW];
    const float c1 = p1[0];
    const float x1 = p1[HW], y1 = p1[2*HW], w1 = p1[3*HW], h1 = p1[4*HW];
    const float c2 = p2[0];
    const float x2 = p2[HW], y2 = p2[2*HW], w2 = p2[3*HW], h2 = p2[4*HW];

    const float fb = (float)b;
    const float fw = (float)w;
    const float fh = (float)h;
    const float t = (float)TT;

    const bool m0 = c0 > thresh;
    so[0]  = m0 ? fb : 0.0f;
    so[1]  = m0 ? (fw + x0) * t : 0.0f;
    so[2]  = m0 ? (fh + y0) * t : 0.0f;
    so[3]  = m0 ? (float)AW0 * __expf(w0) : 0.0f;
    so[4]  = m0 ? (float)AH0 * __expf(h0) : 0.0f;

    const bool m1 = c1 > thresh;
    so[5]  = m1 ? fb : 0.0f;
    so[6]  = m1 ? (fw + x1) * t : 0.0f;
    so[7]  = m1 ? (fh + y1) * t : 0.0f;
    so[8]  = m1 ? (float)AW1 * __expf(w1) : 0.0f;
    so[9]  = m1 ? (float)AH1 * __expf(h1) : 0.0f;

    const bool m2 = c2 > thresh;
    so[10] = m2 ? fb : 0.0f;
    so[11] = m2 ? (fw + x2) * t : 0.0f;
    so[12] = m2 ? (fh + y2) * t : 0.0f;
    so[13] = m2 ? (float)AW2 * __expf(w2) : 0.0f;
    so[14] = m2 ? (float)AH2 * __expf(h2) : 0.0f;
}

__global__ __launch_bounds__(TPB) void detector_decode_kernel(
    const float* __restrict__ in13,
    const float* __restrict__ in26,
    const float* __restrict__ in52,
    const float* __restrict__ pthresh,
    float* __restrict__ out)
{
    __shared__ float s[TPB * 15];

    constexpr int N13 = 32 * 169;            // 5408
    constexpr int N26 = 32 * 676;            // 21632
    constexpr int NTOT = 113568;
    constexpr int GW13 = 169;                // global warp-id bounds
    constexpr int GW26 = 845;

    const float thresh = __ldg(pthresh);     // overlaps all setup

    const int tid   = threadIdx.x;
    const int warp  = tid >> 5;
    const int lane  = tid & 31;
    const int gcell = blockIdx.x * TPB + tid;
    const int gwarp = gcell >> 5;            // warp-uniform (bounds % 32 == 0)

    float* __restrict__ so = s + tid * 15;

    if (gcell < NTOT) {
        if (gwarp < GW13) {
            decode_scale<169, 13, 32, 116, 90, 156, 198, 373, 326>(
                in13, gcell, so, thresh);
        } else if (gwarp < GW26) {
            decode_scale<676, 26, 16, 30, 61, 62, 45, 59, 119>(
                in26, gcell - N13, so, thresh);
        } else {
            decode_scale<2704, 52, 8, 10, 13, 16, 30, 33, 23>(
                in52, gcell - (N13 + N26), so, thresh);
        }
    }

    __syncwarp();

    // Per-warp async-proxy copy-out: this warp's 480 staged floats (1920 B,
    // both sides 16B-aligned since warpCell % 32 == 0) -> contiguous gmem,
    // one cp.async.bulk issued by lane 0. Warp retires independently.
    const int warpCell = blockIdx.x * TPB + warp * 32;
    if (warpCell < NTOT && lane == 0) {
        asm volatile("fence.proxy.async.shared::cta;" ::: "memory");
        const uint32_t src = smem_u32(s + warp * 480);
        float* dstp = out + warpCell * 15;
        asm volatile(
            "cp.async.bulk.global.shared::cta.bulk_group [%0], [%1], %2;"
            :: "l"(dstp), "r"(src), "n"(1920) : "memory");
        asm volatile("cp.async.bulk.commit_group;" ::: "memory");
        asm volatile("cp.async.bulk.wait_group 0;" ::: "memory");
    }
}

extern "C" void kernel_launch(void* const* d_in, const int* in_sizes, int n_in,
                              void* d_out, int out_size)
{
    const float* in13 = (const float*)d_in[0];
    const float* in26 = (const float*)d_in[1];
    const float* in52 = (const float*)d_in[2];
    const float* pthresh = (const float*)d_in[3];
    float* out = (float*)d_out;

    constexpr int NTOT = 113568;
    constexpr int blocks = (NTOT + TPB - 1) / TPB;   // 444 = 3 * 148
    detector_decode_kernel<<<blocks, TPB>>>(in13, in26, in52, pthresh, out);
}

// round 13
// speedup vs baseline: 1.0435x; 1.0435x over previous
#include <cuda_runtime.h>
#include <cstdint>

// YOLO decode, 3 scales fused. Grid = 148 (one CTA per SM), TPB = 768
// (24 warps/SM, same as 3x256 before), but with R8's winning per-warp
// independent epilogue: __syncwarp only, one cp.async.bulk (1920 B) per
// warp, warps retire independently. Decouples CTA-count from the per-CTA
// barrier that regressed R9.

#define TPB 768

__device__ __forceinline__ uint32_t smem_u32(const void* p) {
    return (uint32_t)__cvta_generic_to_shared(p);
}

template<int HW, int W, int TT,
         int AW0, int AH0, int AW1, int AH1, int AW2, int AH2>
__device__ __forceinline__ void decode_scale(const float* __restrict__ in,
                                             int c, float* __restrict__ so,
                                             float thresh)
{
    const int b  = c / HW;            // constexpr -> mul+shift
    const int hw = c - b * HW;
    const int h  = hw / W;
    const int w  = hw - h * W;

    const float* __restrict__ base = in + b * (255 * HW) + hw;
    const float* __restrict__ p0 = base;
    const float* __restrict__ p1 = base + 85  * HW;
    const float* __restrict__ p2 = base + 170 * HW;

    // 15 independent coalesced loads in flight.
    const float c0 = p0[0];
    const float x0 = p0[HW], y0 = p0[2*HW], w0 = p0[3*HW], h0 = p0[4*HW];
    const float c1 = p1[0];
    const float x1 = p1[HW], y1 = p1[2*HW], w1 = p1[3*HW], h1 = p1[4*HW];
    const float c2 = p2[0];
    const float x2 = p2[HW], y2 = p2[2*HW], w2 = p2[3*HW], h2 = p2[4*HW];

    const float fb = (float)b;
    const float fw = (float)w;
    const float fh = (float)h;
    const float t = (float)TT;

    const bool m0 = c0 > thresh;
    so[0]  = m0 ? fb : 0.0f;
    so[1]  = m0 ? (fw + x0) * t : 0.0f;
    so[2]  = m0 ? (fh + y0) * t : 0.0f;
    so[3]  = m0 ? (float)AW0 * __expf(w0) : 0.0f;
    so[4]  = m0 ? (float)AH0 * __expf(h0) : 0.0f;

    const bool m1 = c1 > thresh;
    so[5]  = m1 ? fb : 0.0f;
    so[6]  = m1 ? (fw + x1) * t : 0.0f;
    so[7]  = m1 ? (fh + y1) * t : 0.0f;
    so[8]  = m1 ? (float)AW1 * __expf(w1) : 0.0f;
    so[9]  = m1 ? (float)AH1 * __expf(h1) : 0.0f;

    const bool m2 = c2 > thresh;
    so[10] = m2 ? fb : 0.0f;
    so[11] = m2 ? (fw + x2) * t : 0.0f;
    so[12] = m2 ? (fh + y2) * t : 0.0f;
    so[13] = m2 ? (float)AW2 * __expf(w2) : 0.0f;
    so[14] = m2 ? (float)AH2 * __expf(h2) : 0.0f;
}

__global__ __launch_bounds__(TPB) void detector_decode_kernel(
    const float* __restrict__ in13,
    const float* __restrict__ in26,
    const float* __restrict__ in52,
    const float* __restrict__ pthresh,
    float* __restrict__ out)
{
    __shared__ float s[TPB * 15];            // 46080 B

    constexpr int N13 = 32 * 169;            // 5408
    constexpr int N26 = 32 * 676;            // 21632
    constexpr int NTOT = 113568;
    constexpr int GW13 = 169;                // global warp-id bounds
    constexpr int GW26 = 845;

    const float thresh = __ldg(pthresh);     // overlaps all setup

    const int tid   = threadIdx.x;
    const int warp  = tid >> 5;
    const int lane  = tid & 31;
    const int gcell = blockIdx.x * TPB + tid;
    const int gwarp = gcell >> 5;            // warp-uniform (bounds % 32 == 0)

    float* __restrict__ so = s + tid * 15;

    if (gcell < NTOT) {
        if (gwarp < GW13) {
            decode_scale<169, 13, 32, 116, 90, 156, 198, 373, 326>(
                in13, gcell, so, thresh);
        } else if (gwarp < GW26) {
            decode_scale<676, 26, 16, 30, 61, 62, 45, 59, 119>(
                in26, gcell - N13, so, thresh);
        } else {
            decode_scale<2704, 52, 8, 10, 13, 16, 30, 33, 23>(
                in52, gcell - (N13 + N26), so, thresh);
        }
    }

    __syncwarp();

    // Per-warp async-proxy copy-out: this warp's 480 staged floats (1920 B,
    // both sides 16B-aligned since warpCell % 32 == 0). Warp retires
    // independently — no block barrier.
    const int warpCell = blockIdx.x * TPB + warp * 32;
    if (warpCell < NTOT && lane == 0) {
        asm volatile("fence.proxy.async.shared::cta;" ::: "memory");
        const uint32_t src = smem_u32(s + warp * 480);
        float* dstp = out + warpCell * 15;
        asm volatile(
            "cp.async.bulk.global.shared::cta.bulk_group [%0], [%1], %2;"
            :: "l"(dstp), "r"(src), "n"(1920) : "memory");
        asm volatile("cp.async.bulk.commit_group;" ::: "memory");
        asm volatile("cp.async.bulk.wait_group 0;" ::: "memory");
    }
}

extern "C" void kernel_launch(void* const* d_in, const int* in_sizes, int n_in,
                              void* d_out, int out_size)
{
    const float* in13 = (const float*)d_in[0];
    const float* in26 = (const float*)d_in[1];
    const float* in52 = (const float*)d_in[2];
    const float* pthresh = (const float*)d_in[3];
    float* out = (float*)d_out;

    constexpr int NTOT = 113568;
    constexpr int blocks = (NTOT + TPB - 1) / TPB;   // 148 = one per SM
    detector_decode_kernel<<<blocks, TPB>>>(in13, in26, in52, pthresh, out);
}